// round 11
// baseline (speedup 1.0000x reference)
#include <cuda_runtime.h>
#include <cuda_bf16.h>
#include <math.h>
#include <stdint.h>

#define UU 100000
#define BB 128
#define KK 500
#define KPAD 512
#define NNBH 100
#define NRUNS 10

// ---------------- scratch (no allocations allowed) ----------------
__device__ __align__(256) __nv_bfloat16 g_yb[NRUNS][KPAD][BB]; // normalized rows, bf16
__device__ float2 g_pos[NRUNS][KPAD];
__device__ int    g_uord[NRUNS][KPAD];    // sorted chosen indices (pads = INT_MAX)
__device__ double g_acc[NRUNS][5];        // Sr, Srr, Srd, Sd, Sdd
__device__ unsigned g_done;               // completion ticket

// ---------------- threefry2x32 (JAX legacy layout — validated R2) ----------------
__device__ __forceinline__ unsigned rotl32(unsigned x, int r) {
    return (x << r) | (x >> (32 - r));
}
__device__ __forceinline__ void tf2x32(unsigned x0, unsigned x1,
                                       unsigned& o0, unsigned& o1) {
    const unsigned k0 = 0u, k1 = 42u;
    const unsigned k2 = k0 ^ k1 ^ 0x1BD11BDAu;
    x0 += k0; x1 += k1;
    const int rotA[4] = {13, 15, 26, 6};
    const int rotB[4] = {17, 29, 16, 24};
#pragma unroll
    for (int i = 0; i < 4; i++) { x0 += x1; x1 = rotl32(x1, rotA[i]); x1 ^= x0; }
    x0 += k1; x1 += k2 + 1u;
#pragma unroll
    for (int i = 0; i < 4; i++) { x0 += x1; x1 = rotl32(x1, rotB[i]); x1 ^= x0; }
    x0 += k2; x1 += k0 + 2u;
#pragma unroll
    for (int i = 0; i < 4; i++) { x0 += x1; x1 = rotl32(x1, rotA[i]); x1 ^= x0; }
    x0 += k0; x1 += k1 + 3u;
#pragma unroll
    for (int i = 0; i < 4; i++) { x0 += x1; x1 = rotl32(x1, rotB[i]); x1 ^= x0; }
    x0 += k1; x1 += k2 + 4u;
#pragma unroll
    for (int i = 0; i < 4; i++) { x0 += x1; x1 = rotl32(x1, rotA[i]); x1 ^= x0; }
    x0 += k2; x1 += k0 + 5u;
    o0 = x0; o1 = x1;
}
__device__ __forceinline__ unsigned choice_for(int r) {
    unsigned a0, a1;
    tf2x32((unsigned)r, (unsigned)(r + NRUNS), a0, a1);
    return ((a0 % 100u) * 96u + (a1 % 100u)) % 100u;
}

// ---------------- warp-MMA helpers (baseline PTX, legal on sm_103) ------------
__device__ __forceinline__ uint32_t smem_u32(const void* p) {
    uint32_t a;
    asm("{ .reg .u64 t; cvta.to.shared.u64 t, %1; cvt.u32.u64 %0, t; }" : "=r"(a) : "l"(p));
    return a;
}
__device__ __forceinline__ void ldsm_x4(uint32_t& r0, uint32_t& r1,
                                        uint32_t& r2, uint32_t& r3, uint32_t addr) {
    asm volatile("ldmatrix.sync.aligned.m8n8.x4.shared.b16 {%0,%1,%2,%3}, [%4];"
                 : "=r"(r0), "=r"(r1), "=r"(r2), "=r"(r3) : "r"(addr));
}
__device__ __forceinline__ void mma_bf16(float& c0, float& c1, float& c2, float& c3,
                                         uint32_t a0, uint32_t a1, uint32_t a2, uint32_t a3,
                                         uint32_t b0, uint32_t b1) {
    asm volatile("mma.sync.aligned.m16n8k16.row.col.f32.bf16.bf16.f32 "
                 "{%0,%1,%2,%3}, {%4,%5,%6,%7}, {%8,%9}, {%0,%1,%2,%3};"
                 : "+f"(c0), "+f"(c1), "+f"(c2), "+f"(c3)
                 : "r"(a0), "r"(a1), "r"(a2), "r"(a3), "r"(b0), "r"(b1));
}

// ---------------- cold finalize (float-only, noinline) ----------------
__device__ __noinline__ void do_finalize(float* out) {
    const float P = (float)(KK * (KK - 1) / 2);
    float total = 0.f;
#pragma unroll 1
    for (int r = 0; r < NRUNS; r++) {
        float Sr  = (float)g_acc[r][0];
        float Srr = (float)g_acc[r][1];
        float Srd = (float)g_acc[r][2];
        float Sd  = (float)g_acc[r][3];
        float Sdd = (float)g_acc[r][4];
        float num = Srd - Sr * Sd / P;
        float den = sqrtf((Srr - Sr * Sr / P) * (Sdd - Sd * Sd / P));
        total += (1.0f - num / den) * 0.5f;
    }
    out[0] = total * (1.0f / NRUNS);
}

// ---------------- kernel 0: choice + bitonic sort (per run) ----------------
__global__ void __launch_bounds__(KPAD) k_sort(const int* __restrict__ neigh) {
    __shared__ int sv[KPAD];
    int run = blockIdx.x;
    int t = threadIdx.x;
    __shared__ int s_choice;
    if (t == 0) s_choice = (int)choice_for(run);
    if (t < 5) g_acc[run][t] = 0.0;
    if (blockIdx.x == 0 && t == 0) g_done = 0u;
    __syncthreads();
    int choice = s_choice;
    sv[t] = (t < KK) ? __ldg(&neigh[choice * KK + t]) : 0x7FFFFFFF;
    __syncthreads();
    for (int k = 2; k <= KPAD; k <<= 1) {
        for (int j = k >> 1; j > 0; j >>= 1) {
            int ixj = t ^ j;
            if (ixj > t) {
                int a = sv[t], b = sv[ixj];
                bool up = ((t & k) == 0);
                if ((a > b) == up) { sv[t] = b; sv[ixj] = a; }
            }
            __syncthreads();
        }
    }
    g_uord[run][t] = sv[t];
}

// ---------------- kernel 1: gather + center + normalize -> bf16 row-major ------
__global__ void __launch_bounds__(256) k_gather(const float* __restrict__ feats,
                                                const float* __restrict__ pos) {
    int run = blockIdx.y;
    int warp = threadIdx.x >> 5, lane = threadIdx.x & 31;
    int kbase = blockIdx.x * 16;
    int k0 = kbase + warp * 2;
    int k1 = k0 + 1;

    int u0 = __ldg(&g_uord[run][k0]);
    int u1 = __ldg(&g_uord[run][k1]);
    bool v0ok = (u0 < UU), v1ok = (u1 < UU);

    float a0 = 0.f, a1 = 0.f, a2 = 0.f, a3 = 0.f;
    float b0 = 0.f, b1 = 0.f, b2 = 0.f, b3 = 0.f;
    if (v0ok) {
        a0 = __ldg(&feats[(size_t)(lane      ) * UU + u0]);
        a1 = __ldg(&feats[(size_t)(lane + 32) * UU + u0]);
        a2 = __ldg(&feats[(size_t)(lane + 64) * UU + u0]);
        a3 = __ldg(&feats[(size_t)(lane + 96) * UU + u0]);
    }
    if (v1ok) {
        b0 = __ldg(&feats[(size_t)(lane      ) * UU + u1]);
        b1 = __ldg(&feats[(size_t)(lane + 32) * UU + u1]);
        b2 = __ldg(&feats[(size_t)(lane + 64) * UU + u1]);
        b3 = __ldg(&feats[(size_t)(lane + 96) * UU + u1]);
    }

    {   // k0
        float s = a0 + a1 + a2 + a3;
#pragma unroll
        for (int o = 16; o; o >>= 1) s += __shfl_xor_sync(0xFFFFFFFFu, s, o);
        float mean = s * (1.0f / 128.0f);
        float c0 = a0 - mean, c1 = a1 - mean, c2 = a2 - mean, c3 = a3 - mean;
        float ss = c0 * c0 + c1 * c1 + c2 * c2 + c3 * c3;
#pragma unroll
        for (int o = 16; o; o >>= 1) ss += __shfl_xor_sync(0xFFFFFFFFu, ss, o);
        float inv = v0ok ? rsqrtf(ss) : 0.0f;
        g_yb[run][k0][lane     ] = __float2bfloat16_rn(c0 * inv);
        g_yb[run][k0][lane + 32] = __float2bfloat16_rn(c1 * inv);
        g_yb[run][k0][lane + 64] = __float2bfloat16_rn(c2 * inv);
        g_yb[run][k0][lane + 96] = __float2bfloat16_rn(c3 * inv);
        if (lane == 0)
            g_pos[run][k0] = v0ok ? ((const float2*)pos)[u0] : make_float2(0.f, 0.f);
    }
    {   // k1
        float s = b0 + b1 + b2 + b3;
#pragma unroll
        for (int o = 16; o; o >>= 1) s += __shfl_xor_sync(0xFFFFFFFFu, s, o);
        float mean = s * (1.0f / 128.0f);
        float c0 = b0 - mean, c1 = b1 - mean, c2 = b2 - mean, c3 = b3 - mean;
        float ss = c0 * c0 + c1 * c1 + c2 * c2 + c3 * c3;
#pragma unroll
        for (int o = 16; o; o >>= 1) ss += __shfl_xor_sync(0xFFFFFFFFu, ss, o);
        float inv = v1ok ? rsqrtf(ss) : 0.0f;
        g_yb[run][k1][lane     ] = __float2bfloat16_rn(c0 * inv);
        g_yb[run][k1][lane + 32] = __float2bfloat16_rn(c1 * inv);
        g_yb[run][k1][lane + 64] = __float2bfloat16_rn(c2 * inv);
        g_yb[run][k1][lane + 96] = __float2bfloat16_rn(c3 * inv);
        if (lane == 0)
            g_pos[run][k1] = v1ok ? ((const float2*)pos)[u1] : make_float2(0.f, 0.f);
    }
}

// ---------------- kernel 2: warp-MMA bf16 pair sums + fused finalize ----------
#define NTILE 20
#define NBLK (NRUNS * NTILE)
__constant__ int c_mt[NTILE] = {0,0, 1,1,1,1, 2,2,2,2,2,2, 3,3,3,3,3,3,3,3};
__constant__ int c_nt[NTILE] = {0,1, 0,1,2,3, 0,1,2,3,4,5, 0,1,2,3,4,5,6,7};

#define ASTR 136                        // bf16 elems per smem row = 272B = 17*16B
#define SMA_BYTES (128 * ASTR * 2)      // 34816
#define SMB_BYTES (64 * ASTR * 2)       // 17408
#define SM_POSI   (SMA_BYTES + SMB_BYTES)           // float2[128] = 1024
#define SM_POSJ   (SM_POSI + 1024)                  // float2[64]  = 512
#define SM_TOTAL  (SM_POSJ + 512)

__global__ void __launch_bounds__(256) k_pairs(float* __restrict__ out) {
    extern __shared__ char smem[];
    __nv_bfloat16* sA = (__nv_bfloat16*)smem;
    __nv_bfloat16* sB = (__nv_bfloat16*)(smem + SMA_BYTES);
    float2* posi = (float2*)(smem + SM_POSI);
    float2* posj = (float2*)(smem + SM_POSJ);

    int run = blockIdx.x / NTILE;
    int t   = blockIdx.x % NTILE;
    int i0 = c_mt[t] * 128, j0 = c_nt[t] * 64;

    int tid = threadIdx.x;
    int wid = tid >> 5, lane = tid & 31;
    int wm = wid >> 1, wn = wid & 1;     // 4x2 warp grid; warp tile 32x32

    for (int idx = tid; idx < 128 * 16; idx += 256) {
        int row = idx >> 4, c16 = idx & 15;
        ((float4*)(sA + row * ASTR))[c16] = ((const float4*)&g_yb[run][i0 + row][0])[c16];
    }
    for (int idx = tid; idx < 64 * 16; idx += 256) {
        int row = idx >> 4, c16 = idx & 15;
        ((float4*)(sB + row * ASTR))[c16] = ((const float4*)&g_yb[run][j0 + row][0])[c16];
    }
    if (tid < 128) posi[tid] = g_pos[run][i0 + tid];
    else if (tid < 192) posj[tid - 128] = g_pos[run][j0 + tid - 128];
    __syncthreads();

    uint32_t sbA = smem_u32(sA), sbB = smem_u32(sB);

    float acc[2][4][4];
#pragma unroll
    for (int mb = 0; mb < 2; mb++)
#pragma unroll
        for (int nb = 0; nb < 4; nb++)
#pragma unroll
            for (int v = 0; v < 4; v++) acc[mb][nb][v] = 0.f;

    uint32_t arow = (uint32_t)(wm * 32 + (lane & 15));
    uint32_t aoff = arow * (ASTR * 2) + ((lane >> 4) << 4);
    uint32_t brow = (uint32_t)(wn * 32 + (lane & 7) + ((lane >> 4) << 3));
    uint32_t boff = brow * (ASTR * 2) + (((lane >> 3) & 1) << 4);

#pragma unroll
    for (int s = 0; s < 8; s++) {
        uint32_t kb = (uint32_t)(s * 32);
        uint32_t a0[4], a1[4], b0[4], b1[4];
        ldsm_x4(a0[0], a0[1], a0[2], a0[3], sbA + aoff + kb);
        ldsm_x4(a1[0], a1[1], a1[2], a1[3], sbA + aoff + 16 * (ASTR * 2) + kb);
        ldsm_x4(b0[0], b0[1], b0[2], b0[3], sbB + boff + kb);
        ldsm_x4(b1[0], b1[1], b1[2], b1[3], sbB + boff + 16 * (ASTR * 2) + kb);
#pragma unroll
        for (int mb = 0; mb < 2; mb++) {
            uint32_t* a = (mb == 0) ? a0 : a1;
            mma_bf16(acc[mb][0][0], acc[mb][0][1], acc[mb][0][2], acc[mb][0][3],
                     a[0], a[1], a[2], a[3], b0[0], b0[1]);
            mma_bf16(acc[mb][1][0], acc[mb][1][1], acc[mb][1][2], acc[mb][1][3],
                     a[0], a[1], a[2], a[3], b0[2], b0[3]);
            mma_bf16(acc[mb][2][0], acc[mb][2][1], acc[mb][2][2], acc[mb][2][3],
                     a[0], a[1], a[2], a[3], b1[0], b1[1]);
            mma_bf16(acc[mb][3][0], acc[mb][3][1], acc[mb][3][2], acc[mb][3][3],
                     a[0], a[1], a[2], a[3], b1[2], b1[3]);
        }
    }

    float sr = 0.f, srr = 0.f, srd = 0.f, sd = 0.f, sdd = 0.f;
    int r4 = lane >> 2, c2 = (lane & 3) * 2;
#pragma unroll
    for (int mb = 0; mb < 2; mb++) {
#pragma unroll
        for (int nb = 0; nb < 4; nb++) {
#pragma unroll
            for (int v = 0; v < 4; v++) {
                int il = wm * 32 + mb * 16 + r4 + ((v >> 1) << 3);
                int jl = wn * 32 + nb * 8 + c2 + (v & 1);
                int gi = i0 + il, gj = j0 + jl;
                if (gi < KK && gj < gi) {
                    float rv = acc[mb][nb][v];
                    float2 P = posi[il];
                    float2 Q = posj[jl];
                    float dx = P.x - Q.x, dy = P.y - Q.y;
                    float ds = 1.0f / (sqrtf(dx * dx + dy * dy) + 1.0f);
                    sr += rv; srr += rv * rv; srd += rv * ds;
                    sd += ds; sdd += ds * ds;
                }
            }
        }
    }

    float vals[5] = {sr, srr, srd, sd, sdd};
    __shared__ double red[8][5];
#pragma unroll
    for (int v = 0; v < 5; v++) {
        float x = vals[v];
#pragma unroll
        for (int o = 16; o; o >>= 1) x += __shfl_xor_sync(0xFFFFFFFFu, x, o);
        if (lane == 0) red[wid][v] = (double)x;
    }
    __syncthreads();
    if (tid < 5) {
        double s = 0.0;
#pragma unroll
        for (int w = 0; w < 8; w++) s += red[w][tid];
        atomicAdd(&g_acc[run][tid], s);
    }
    __syncthreads();

    // fused finalize: last block (ticket) runs cold float-only epilogue
    __shared__ unsigned s_ticket;
    if (tid == 0) {
        __threadfence();
        s_ticket = atomicAdd(&g_done, 1u);
    }
    __syncthreads();
    if (s_ticket == NBLK - 1 && tid == 0) {
        __threadfence();
        do_finalize(out);
    }
}

// ---------------- launch ----------------
extern "C" void kernel_launch(void* const* d_in, const int* in_sizes, int n_in,
                              void* d_out, int out_size) {
    const float* feats = (const float*)d_in[0];   // (128, 100000) f32
    const float* pos   = (const float*)d_in[1];   // (100000, 2)   f32
    const int*   neigh = (const int*)  d_in[2];   // (100, 500)    i32

    cudaFuncSetAttribute(k_pairs, cudaFuncAttributeMaxDynamicSharedMemorySize,
                         SM_TOTAL);

    k_sort<<<NRUNS, KPAD>>>(neigh);
    k_gather<<<dim3(32, NRUNS), 256>>>(feats, pos);
    k_pairs<<<NBLK, 256, SM_TOTAL>>>((float*)d_out);
}

// round 12
// speedup vs baseline: 1.1085x; 1.1085x over previous
#include <cuda_runtime.h>
#include <cuda_bf16.h>
#include <math.h>
#include <stdint.h>

#define UU 100000
#define BB 128
#define KK 500
#define KPAD 512
#define NNBH 100
#define NRUNS 10

// ---------------- scratch (no allocations allowed) ----------------
__device__ __align__(256) __nv_bfloat16 g_yb[NRUNS][KPAD][BB]; // normalized rows, bf16
__device__ float2 g_pos[NRUNS][KPAD];
__device__ double g_acc[NRUNS][5];        // Sr, Srr, Srd, Sd, Sdd
__device__ unsigned g_done;               // completion ticket

// ---------------- threefry2x32 (JAX legacy layout — validated R2) ----------------
__device__ __forceinline__ unsigned rotl32(unsigned x, int r) {
    return (x << r) | (x >> (32 - r));
}
__device__ __forceinline__ void tf2x32(unsigned x0, unsigned x1,
                                       unsigned& o0, unsigned& o1) {
    const unsigned k0 = 0u, k1 = 42u;
    const unsigned k2 = k0 ^ k1 ^ 0x1BD11BDAu;
    x0 += k0; x1 += k1;
    const int rotA[4] = {13, 15, 26, 6};
    const int rotB[4] = {17, 29, 16, 24};
#pragma unroll
    for (int i = 0; i < 4; i++) { x0 += x1; x1 = rotl32(x1, rotA[i]); x1 ^= x0; }
    x0 += k1; x1 += k2 + 1u;
#pragma unroll
    for (int i = 0; i < 4; i++) { x0 += x1; x1 = rotl32(x1, rotB[i]); x1 ^= x0; }
    x0 += k2; x1 += k0 + 2u;
#pragma unroll
    for (int i = 0; i < 4; i++) { x0 += x1; x1 = rotl32(x1, rotA[i]); x1 ^= x0; }
    x0 += k0; x1 += k1 + 3u;
#pragma unroll
    for (int i = 0; i < 4; i++) { x0 += x1; x1 = rotl32(x1, rotB[i]); x1 ^= x0; }
    x0 += k1; x1 += k2 + 4u;
#pragma unroll
    for (int i = 0; i < 4; i++) { x0 += x1; x1 = rotl32(x1, rotA[i]); x1 ^= x0; }
    x0 += k2; x1 += k0 + 5u;
    o0 = x0; o1 = x1;
}
__device__ __forceinline__ unsigned choice_for(int r) {
    unsigned a0, a1;
    tf2x32((unsigned)r, (unsigned)(r + NRUNS), a0, a1);
    return ((a0 % 100u) * 96u + (a1 % 100u)) % 100u;
}

// ---------------- warp-MMA helpers (baseline PTX, legal on sm_103) ------------
__device__ __forceinline__ uint32_t smem_u32(const void* p) {
    uint32_t a;
    asm("{ .reg .u64 t; cvta.to.shared.u64 t, %1; cvt.u32.u64 %0, t; }" : "=r"(a) : "l"(p));
    return a;
}
__device__ __forceinline__ void ldsm_x4(uint32_t& r0, uint32_t& r1,
                                        uint32_t& r2, uint32_t& r3, uint32_t addr) {
    asm volatile("ldmatrix.sync.aligned.m8n8.x4.shared.b16 {%0,%1,%2,%3}, [%4];"
                 : "=r"(r0), "=r"(r1), "=r"(r2), "=r"(r3) : "r"(addr));
}
__device__ __forceinline__ void mma_bf16(float& c0, float& c1, float& c2, float& c3,
                                         uint32_t a0, uint32_t a1, uint32_t a2, uint32_t a3,
                                         uint32_t b0, uint32_t b1) {
    asm volatile("mma.sync.aligned.m16n8k16.row.col.f32.bf16.bf16.f32 "
                 "{%0,%1,%2,%3}, {%4,%5,%6,%7}, {%8,%9}, {%0,%1,%2,%3};"
                 : "+f"(c0), "+f"(c1), "+f"(c2), "+f"(c3)
                 : "r"(a0), "r"(a1), "r"(a2), "r"(a3), "r"(b0), "r"(b1));
}

// ---------------- cold finalize (float-only, noinline) ----------------
__device__ __noinline__ void do_finalize(float* out) {
    const float P = (float)(KK * (KK - 1) / 2);
    float total = 0.f;
#pragma unroll 1
    for (int r = 0; r < NRUNS; r++) {
        float Sr  = (float)g_acc[r][0];
        float Srr = (float)g_acc[r][1];
        float Srd = (float)g_acc[r][2];
        float Sd  = (float)g_acc[r][3];
        float Sdd = (float)g_acc[r][4];
        float num = Srd - Sr * Sd / P;
        float den = sqrtf((Srr - Sr * Sr / P) * (Sdd - Sd * Sd / P));
        total += (1.0f - num / den) * 0.5f;
    }
    out[0] = total * (1.0f / NRUNS);
}

// ---------------- kernel 1: gather + center + normalize -> bf16 row-major ------
// grid (32, NRUNS) x 256; warp w handles k = bx*16 + 2w, +1 in ORIGINAL order
// (tril mask in k_pairs uses original indices -> exactly the reference pair set).
__global__ void __launch_bounds__(256) k_gather(const float* __restrict__ feats,
                                                const float* __restrict__ pos,
                                                const int* __restrict__ neigh) {
    int run = blockIdx.y;
    __shared__ int s_choice;
    if (threadIdx.x == 0) s_choice = (int)choice_for(run);
    if (blockIdx.x == 0 && blockIdx.y == 0) {
        if (threadIdx.x < NRUNS * 5) ((double*)g_acc)[threadIdx.x] = 0.0;
        if (threadIdx.x == 64) g_done = 0u;
    }
    __syncthreads();
    int choice = s_choice;
    int warp = threadIdx.x >> 5, lane = threadIdx.x & 31;
    int kbase = blockIdx.x * 16;
    int k0 = kbase + warp * 2;
    int k1 = k0 + 1;

    bool v0ok = (k0 < KK), v1ok = (k1 < KK);
    int u0 = v0ok ? __ldg(&neigh[choice * KK + k0]) : 0;
    int u1 = v1ok ? __ldg(&neigh[choice * KK + k1]) : 0;

    float a0 = 0.f, a1 = 0.f, a2 = 0.f, a3 = 0.f;
    float b0 = 0.f, b1 = 0.f, b2 = 0.f, b3 = 0.f;
    if (v0ok) {
        a0 = __ldg(&feats[(size_t)(lane      ) * UU + u0]);
        a1 = __ldg(&feats[(size_t)(lane + 32) * UU + u0]);
        a2 = __ldg(&feats[(size_t)(lane + 64) * UU + u0]);
        a3 = __ldg(&feats[(size_t)(lane + 96) * UU + u0]);
    }
    if (v1ok) {
        b0 = __ldg(&feats[(size_t)(lane      ) * UU + u1]);
        b1 = __ldg(&feats[(size_t)(lane + 32) * UU + u1]);
        b2 = __ldg(&feats[(size_t)(lane + 64) * UU + u1]);
        b3 = __ldg(&feats[(size_t)(lane + 96) * UU + u1]);
    }

    {   // k0
        float s = a0 + a1 + a2 + a3;
#pragma unroll
        for (int o = 16; o; o >>= 1) s += __shfl_xor_sync(0xFFFFFFFFu, s, o);
        float mean = s * (1.0f / 128.0f);
        float c0 = a0 - mean, c1 = a1 - mean, c2 = a2 - mean, c3 = a3 - mean;
        float ss = c0 * c0 + c1 * c1 + c2 * c2 + c3 * c3;
#pragma unroll
        for (int o = 16; o; o >>= 1) ss += __shfl_xor_sync(0xFFFFFFFFu, ss, o);
        float inv = v0ok ? rsqrtf(ss) : 0.0f;
        g_yb[run][k0][lane     ] = __float2bfloat16_rn(c0 * inv);
        g_yb[run][k0][lane + 32] = __float2bfloat16_rn(c1 * inv);
        g_yb[run][k0][lane + 64] = __float2bfloat16_rn(c2 * inv);
        g_yb[run][k0][lane + 96] = __float2bfloat16_rn(c3 * inv);
        if (lane == 0)
            g_pos[run][k0] = v0ok ? ((const float2*)pos)[u0] : make_float2(0.f, 0.f);
    }
    {   // k1
        float s = b0 + b1 + b2 + b3;
#pragma unroll
        for (int o = 16; o; o >>= 1) s += __shfl_xor_sync(0xFFFFFFFFu, s, o);
        float mean = s * (1.0f / 128.0f);
        float c0 = b0 - mean, c1 = b1 - mean, c2 = b2 - mean, c3 = b3 - mean;
        float ss = c0 * c0 + c1 * c1 + c2 * c2 + c3 * c3;
#pragma unroll
        for (int o = 16; o; o >>= 1) ss += __shfl_xor_sync(0xFFFFFFFFu, ss, o);
        float inv = v1ok ? rsqrtf(ss) : 0.0f;
        g_yb[run][k1][lane     ] = __float2bfloat16_rn(c0 * inv);
        g_yb[run][k1][lane + 32] = __float2bfloat16_rn(c1 * inv);
        g_yb[run][k1][lane + 64] = __float2bfloat16_rn(c2 * inv);
        g_yb[run][k1][lane + 96] = __float2bfloat16_rn(c3 * inv);
        if (lane == 0)
            g_pos[run][k1] = v1ok ? ((const float2*)pos)[u1] : make_float2(0.f, 0.f);
    }
}

// ---------------- kernel 2: warp-MMA bf16 pair sums + fused finalize ----------
#define NTILE 20
#define NBLK (NRUNS * NTILE)
__constant__ int c_mt[NTILE] = {0,0, 1,1,1,1, 2,2,2,2,2,2, 3,3,3,3,3,3,3,3};
__constant__ int c_nt[NTILE] = {0,1, 0,1,2,3, 0,1,2,3,4,5, 0,1,2,3,4,5,6,7};

#define ASTR 136                        // bf16 elems per smem row = 272B = 17*16B
#define SMA_BYTES (128 * ASTR * 2)      // 34816
#define SMB_BYTES (64 * ASTR * 2)       // 17408
#define SM_POSI   (SMA_BYTES + SMB_BYTES)           // float2[128] = 1024
#define SM_POSJ   (SM_POSI + 1024)                  // float2[64]  = 512
#define SM_TOTAL  (SM_POSJ + 512)

__global__ void __launch_bounds__(256) k_pairs(float* __restrict__ out) {
    extern __shared__ char smem[];
    __nv_bfloat16* sA = (__nv_bfloat16*)smem;
    __nv_bfloat16* sB = (__nv_bfloat16*)(smem + SMA_BYTES);
    float2* posi = (float2*)(smem + SM_POSI);
    float2* posj = (float2*)(smem + SM_POSJ);

    int run = blockIdx.x / NTILE;
    int t   = blockIdx.x % NTILE;
    int i0 = c_mt[t] * 128, j0 = c_nt[t] * 64;

    int tid = threadIdx.x;
    int wid = tid >> 5, lane = tid & 31;
    int wm = wid >> 1, wn = wid & 1;     // 4x2 warp grid; warp tile 32x32

    for (int idx = tid; idx < 128 * 16; idx += 256) {
        int row = idx >> 4, c16 = idx & 15;
        ((float4*)(sA + row * ASTR))[c16] = ((const float4*)&g_yb[run][i0 + row][0])[c16];
    }
    for (int idx = tid; idx < 64 * 16; idx += 256) {
        int row = idx >> 4, c16 = idx & 15;
        ((float4*)(sB + row * ASTR))[c16] = ((const float4*)&g_yb[run][j0 + row][0])[c16];
    }
    if (tid < 128) posi[tid] = g_pos[run][i0 + tid];
    else if (tid < 192) posj[tid - 128] = g_pos[run][j0 + tid - 128];
    __syncthreads();

    uint32_t sbA = smem_u32(sA), sbB = smem_u32(sB);

    float acc[2][4][4];
#pragma unroll
    for (int mb = 0; mb < 2; mb++)
#pragma unroll
        for (int nb = 0; nb < 4; nb++)
#pragma unroll
            for (int v = 0; v < 4; v++) acc[mb][nb][v] = 0.f;

    uint32_t arow = (uint32_t)(wm * 32 + (lane & 15));
    uint32_t aoff = arow * (ASTR * 2) + ((lane >> 4) << 4);
    uint32_t brow = (uint32_t)(wn * 32 + (lane & 7) + ((lane >> 4) << 3));
    uint32_t boff = brow * (ASTR * 2) + (((lane >> 3) & 1) << 4);

#pragma unroll
    for (int s = 0; s < 8; s++) {
        uint32_t kb = (uint32_t)(s * 32);
        uint32_t a0[4], a1[4], b0[4], b1[4];
        ldsm_x4(a0[0], a0[1], a0[2], a0[3], sbA + aoff + kb);
        ldsm_x4(a1[0], a1[1], a1[2], a1[3], sbA + aoff + 16 * (ASTR * 2) + kb);
        ldsm_x4(b0[0], b0[1], b0[2], b0[3], sbB + boff + kb);
        ldsm_x4(b1[0], b1[1], b1[2], b1[3], sbB + boff + 16 * (ASTR * 2) + kb);
#pragma unroll
        for (int mb = 0; mb < 2; mb++) {
            uint32_t* a = (mb == 0) ? a0 : a1;
            mma_bf16(acc[mb][0][0], acc[mb][0][1], acc[mb][0][2], acc[mb][0][3],
                     a[0], a[1], a[2], a[3], b0[0], b0[1]);
            mma_bf16(acc[mb][1][0], acc[mb][1][1], acc[mb][1][2], acc[mb][1][3],
                     a[0], a[1], a[2], a[3], b0[2], b0[3]);
            mma_bf16(acc[mb][2][0], acc[mb][2][1], acc[mb][2][2], acc[mb][2][3],
                     a[0], a[1], a[2], a[3], b1[0], b1[1]);
            mma_bf16(acc[mb][3][0], acc[mb][3][1], acc[mb][3][2], acc[mb][3][3],
                     a[0], a[1], a[2], a[3], b1[2], b1[3]);
        }
    }

    float sr = 0.f, srr = 0.f, srd = 0.f, sd = 0.f, sdd = 0.f;
    int r4 = lane >> 2, c2 = (lane & 3) * 2;
#pragma unroll
    for (int mb = 0; mb < 2; mb++) {
#pragma unroll
        for (int nb = 0; nb < 4; nb++) {
#pragma unroll
            for (int v = 0; v < 4; v++) {
                int il = wm * 32 + mb * 16 + r4 + ((v >> 1) << 3);
                int jl = wn * 32 + nb * 8 + c2 + (v & 1);
                int gi = i0 + il, gj = j0 + jl;
                if (gi < KK && gj < gi) {
                    float rv = acc[mb][nb][v];
                    float2 P = posi[il];
                    float2 Q = posj[jl];
                    float dx = P.x - Q.x, dy = P.y - Q.y;
                    float ds = 1.0f / (sqrtf(dx * dx + dy * dy) + 1.0f);
                    sr += rv; srr += rv * rv; srd += rv * ds;
                    sd += ds; sdd += ds * ds;
                }
            }
        }
    }

    float vals[5] = {sr, srr, srd, sd, sdd};
    __shared__ double red[8][5];
#pragma unroll
    for (int v = 0; v < 5; v++) {
        float x = vals[v];
#pragma unroll
        for (int o = 16; o; o >>= 1) x += __shfl_xor_sync(0xFFFFFFFFu, x, o);
        if (lane == 0) red[wid][v] = (double)x;
    }
    __syncthreads();
    if (tid < 5) {
        double s = 0.0;
#pragma unroll
        for (int w = 0; w < 8; w++) s += red[w][tid];
        atomicAdd(&g_acc[run][tid], s);
    }
    __syncthreads();

    // fused finalize: last block (ticket) runs cold float-only epilogue
    __shared__ unsigned s_ticket;
    if (tid == 0) {
        __threadfence();
        s_ticket = atomicAdd(&g_done, 1u);
    }
    __syncthreads();
    if (s_ticket == NBLK - 1 && tid == 0) {
        __threadfence();
        do_finalize(out);
    }
}

// ---------------- launch ----------------
extern "C" void kernel_launch(void* const* d_in, const int* in_sizes, int n_in,
                              void* d_out, int out_size) {
    const float* feats = (const float*)d_in[0];   // (128, 100000) f32
    const float* pos   = (const float*)d_in[1];   // (100000, 2)   f32
    const int*   neigh = (const int*)  d_in[2];   // (100, 500)    i32

    cudaFuncSetAttribute(k_pairs, cudaFuncAttributeMaxDynamicSharedMemorySize,
                         SM_TOTAL);

    k_gather<<<dim3(32, NRUNS), 256>>>(feats, pos, neigh);
    k_pairs<<<NBLK, 256, SM_TOTAL>>>((float*)d_out);
}

// round 13
// speedup vs baseline: 1.1757x; 1.0607x over previous
#include <cuda_runtime.h>
#include <cuda_bf16.h>
#include <math.h>
#include <stdint.h>

#define UU 100000
#define BB 128
#define KK 500
#define KPAD 512
#define NNBH 100
#define NRUNS 10

// ---------------- scratch (no allocations allowed) ----------------
__device__ __align__(256) __nv_bfloat16 g_yb[NRUNS][KPAD][BB]; // normalized rows, bf16
__device__ float2 g_pos[NRUNS][KPAD];
__device__ double g_acc[NRUNS][5];        // Sr, Srr, Srd, Sd, Sdd
__device__ unsigned g_done;               // completion ticket

// ---------------- threefry2x32 (JAX legacy layout — validated R2) ----------------
__device__ __forceinline__ unsigned rotl32(unsigned x, int r) {
    return (x << r) | (x >> (32 - r));
}
__device__ __forceinline__ void tf2x32(unsigned x0, unsigned x1,
                                       unsigned& o0, unsigned& o1) {
    const unsigned k0 = 0u, k1 = 42u;
    const unsigned k2 = k0 ^ k1 ^ 0x1BD11BDAu;
    x0 += k0; x1 += k1;
    const int rotA[4] = {13, 15, 26, 6};
    const int rotB[4] = {17, 29, 16, 24};
#pragma unroll
    for (int i = 0; i < 4; i++) { x0 += x1; x1 = rotl32(x1, rotA[i]); x1 ^= x0; }
    x0 += k1; x1 += k2 + 1u;
#pragma unroll
    for (int i = 0; i < 4; i++) { x0 += x1; x1 = rotl32(x1, rotB[i]); x1 ^= x0; }
    x0 += k2; x1 += k0 + 2u;
#pragma unroll
    for (int i = 0; i < 4; i++) { x0 += x1; x1 = rotl32(x1, rotA[i]); x1 ^= x0; }
    x0 += k0; x1 += k1 + 3u;
#pragma unroll
    for (int i = 0; i < 4; i++) { x0 += x1; x1 = rotl32(x1, rotB[i]); x1 ^= x0; }
    x0 += k1; x1 += k2 + 4u;
#pragma unroll
    for (int i = 0; i < 4; i++) { x0 += x1; x1 = rotl32(x1, rotA[i]); x1 ^= x0; }
    x0 += k2; x1 += k0 + 5u;
    o0 = x0; o1 = x1;
}
__device__ __forceinline__ unsigned choice_for(int r) {
    unsigned a0, a1;
    tf2x32((unsigned)r, (unsigned)(r + NRUNS), a0, a1);
    return ((a0 % 100u) * 96u + (a1 % 100u)) % 100u;
}

// ---------------- warp-MMA helpers (baseline PTX, legal on sm_103) ------------
__device__ __forceinline__ uint32_t smem_u32(const void* p) {
    uint32_t a;
    asm("{ .reg .u64 t; cvta.to.shared.u64 t, %1; cvt.u32.u64 %0, t; }" : "=r"(a) : "l"(p));
    return a;
}
__device__ __forceinline__ void ldsm_x4(uint32_t& r0, uint32_t& r1,
                                        uint32_t& r2, uint32_t& r3, uint32_t addr) {
    asm volatile("ldmatrix.sync.aligned.m8n8.x4.shared.b16 {%0,%1,%2,%3}, [%4];"
                 : "=r"(r0), "=r"(r1), "=r"(r2), "=r"(r3) : "r"(addr));
}
__device__ __forceinline__ void mma_bf16(float& c0, float& c1, float& c2, float& c3,
                                         uint32_t a0, uint32_t a1, uint32_t a2, uint32_t a3,
                                         uint32_t b0, uint32_t b1) {
    asm volatile("mma.sync.aligned.m16n8k16.row.col.f32.bf16.bf16.f32 "
                 "{%0,%1,%2,%3}, {%4,%5,%6,%7}, {%8,%9}, {%0,%1,%2,%3};"
                 : "+f"(c0), "+f"(c1), "+f"(c2), "+f"(c3)
                 : "r"(a0), "r"(a1), "r"(a2), "r"(a3), "r"(b0), "r"(b1));
}

// ---------------- cold finalize (float-only, noinline) ----------------
__device__ __noinline__ void do_finalize(float* out) {
    const float P = (float)(KK * (KK - 1) / 2);
    float total = 0.f;
#pragma unroll 1
    for (int r = 0; r < NRUNS; r++) {
        float Sr  = (float)g_acc[r][0];
        float Srr = (float)g_acc[r][1];
        float Srd = (float)g_acc[r][2];
        float Sd  = (float)g_acc[r][3];
        float Sdd = (float)g_acc[r][4];
        float num = Srd - Sr * Sd / P;
        float den = sqrtf((Srr - Sr * Sr / P) * (Sdd - Sd * Sd / P));
        total += (1.0f - num / den) * 0.5f;
    }
    out[0] = total * (1.0f / NRUNS);
}

// ---------------- kernel 1: gather + center + normalize -> bf16 row-major ------
__global__ void __launch_bounds__(256) k_gather(const float* __restrict__ feats,
                                                const float* __restrict__ pos,
                                                const int* __restrict__ neigh) {
    int run = blockIdx.y;
    __shared__ int s_choice;
    if (threadIdx.x == 0) s_choice = (int)choice_for(run);
    if (blockIdx.x == 0 && blockIdx.y == 0) {
        if (threadIdx.x < NRUNS * 5) ((double*)g_acc)[threadIdx.x] = 0.0;
        if (threadIdx.x == 64) g_done = 0u;
    }
    __syncthreads();
    int choice = s_choice;
    int warp = threadIdx.x >> 5, lane = threadIdx.x & 31;
    int kbase = blockIdx.x * 16;
    int k0 = kbase + warp * 2;
    int k1 = k0 + 1;

    bool v0ok = (k0 < KK), v1ok = (k1 < KK);
    int u0 = v0ok ? __ldg(&neigh[choice * KK + k0]) : 0;
    int u1 = v1ok ? __ldg(&neigh[choice * KK + k1]) : 0;

    float a0 = 0.f, a1 = 0.f, a2 = 0.f, a3 = 0.f;
    float b0 = 0.f, b1 = 0.f, b2 = 0.f, b3 = 0.f;
    if (v0ok) {
        a0 = __ldg(&feats[(size_t)(lane      ) * UU + u0]);
        a1 = __ldg(&feats[(size_t)(lane + 32) * UU + u0]);
        a2 = __ldg(&feats[(size_t)(lane + 64) * UU + u0]);
        a3 = __ldg(&feats[(size_t)(lane + 96) * UU + u0]);
    }
    if (v1ok) {
        b0 = __ldg(&feats[(size_t)(lane      ) * UU + u1]);
        b1 = __ldg(&feats[(size_t)(lane + 32) * UU + u1]);
        b2 = __ldg(&feats[(size_t)(lane + 64) * UU + u1]);
        b3 = __ldg(&feats[(size_t)(lane + 96) * UU + u1]);
    }

    {   // k0
        float s = a0 + a1 + a2 + a3;
#pragma unroll
        for (int o = 16; o; o >>= 1) s += __shfl_xor_sync(0xFFFFFFFFu, s, o);
        float mean = s * (1.0f / 128.0f);
        float c0 = a0 - mean, c1 = a1 - mean, c2 = a2 - mean, c3 = a3 - mean;
        float ss = c0 * c0 + c1 * c1 + c2 * c2 + c3 * c3;
#pragma unroll
        for (int o = 16; o; o >>= 1) ss += __shfl_xor_sync(0xFFFFFFFFu, ss, o);
        float inv = v0ok ? rsqrtf(ss) : 0.0f;
        g_yb[run][k0][lane     ] = __float2bfloat16_rn(c0 * inv);
        g_yb[run][k0][lane + 32] = __float2bfloat16_rn(c1 * inv);
        g_yb[run][k0][lane + 64] = __float2bfloat16_rn(c2 * inv);
        g_yb[run][k0][lane + 96] = __float2bfloat16_rn(c3 * inv);
        if (lane == 0)
            g_pos[run][k0] = v0ok ? ((const float2*)pos)[u0] : make_float2(0.f, 0.f);
    }
    {   // k1
        float s = b0 + b1 + b2 + b3;
#pragma unroll
        for (int o = 16; o; o >>= 1) s += __shfl_xor_sync(0xFFFFFFFFu, s, o);
        float mean = s * (1.0f / 128.0f);
        float c0 = b0 - mean, c1 = b1 - mean, c2 = b2 - mean, c3 = b3 - mean;
        float ss = c0 * c0 + c1 * c1 + c2 * c2 + c3 * c3;
#pragma unroll
        for (int o = 16; o; o >>= 1) ss += __shfl_xor_sync(0xFFFFFFFFu, ss, o);
        float inv = v1ok ? rsqrtf(ss) : 0.0f;
        g_yb[run][k1][lane     ] = __float2bfloat16_rn(c0 * inv);
        g_yb[run][k1][lane + 32] = __float2bfloat16_rn(c1 * inv);
        g_yb[run][k1][lane + 64] = __float2bfloat16_rn(c2 * inv);
        g_yb[run][k1][lane + 96] = __float2bfloat16_rn(c3 * inv);
        if (lane == 0)
            g_pos[run][k1] = v1ok ? ((const float2*)pos)[u1] : make_float2(0.f, 0.f);
    }
}

// ---------------- kernel 2: warp-MMA bf16 pair sums (64x64 tiles) + finalize ---
// Lower-triangle tiles: mt 0..7, nt 0..mt -> 36 tiles/run -> 360 blocks x 128 thr.
#define NTILE 36
#define NBLK (NRUNS * NTILE)

#define ASTR 136                        // bf16 elems per smem row = 272B = 17*16B
#define SMT_BYTES (64 * ASTR * 2)       // 17408 per tile
#define SM_POSI   (2 * SMT_BYTES)       // float2[64] = 512
#define SM_POSJ   (SM_POSI + 512)
#define SM_TOTAL  (SM_POSJ + 512)

__global__ void __launch_bounds__(128) k_pairs(float* __restrict__ out) {
    extern __shared__ char smem[];
    __nv_bfloat16* sA = (__nv_bfloat16*)smem;
    __nv_bfloat16* sB = (__nv_bfloat16*)(smem + SMT_BYTES);
    float2* posi = (float2*)(smem + SM_POSI);
    float2* posj = (float2*)(smem + SM_POSJ);

    int run = blockIdx.x / NTILE;
    int t   = blockIdx.x % NTILE;
    int mt = 0;
    while ((mt + 1) * (mt + 2) / 2 <= t) mt++;
    int nt = t - mt * (mt + 1) / 2;
    int i0 = mt * 64, j0 = nt * 64;
    bool diag = (mt == nt);

    int tid = threadIdx.x;
    int wid = tid >> 5, lane = tid & 31;
    int wm = wid >> 1, wn = wid & 1;     // 2x2 warp grid; warp tile 32x32

    // load A tile (64x128 bf16); B only when off-diagonal (else alias A)
#pragma unroll
    for (int it = 0; it < 8; it++) {
        int idx = tid + it * 128;        // 64*16 = 1024 total
        int row = idx >> 4, c16 = idx & 15;
        ((float4*)(sA + row * ASTR))[c16] = ((const float4*)&g_yb[run][i0 + row][0])[c16];
    }
    if (!diag) {
#pragma unroll
        for (int it = 0; it < 8; it++) {
            int idx = tid + it * 128;
            int row = idx >> 4, c16 = idx & 15;
            ((float4*)(sB + row * ASTR))[c16] = ((const float4*)&g_yb[run][j0 + row][0])[c16];
        }
    }
    if (tid < 64) posi[tid] = g_pos[run][i0 + tid];
    else if (tid < 128 && !diag) posj[tid - 64] = g_pos[run][j0 + tid - 64];
    __syncthreads();

    __nv_bfloat16* sBe = diag ? sA : sB;
    float2* posje = diag ? posi : posj;
    uint32_t sbA = smem_u32(sA), sbB = smem_u32(sBe);

    float acc[2][4][4];
#pragma unroll
    for (int mb = 0; mb < 2; mb++)
#pragma unroll
        for (int nb = 0; nb < 4; nb++)
#pragma unroll
            for (int v = 0; v < 4; v++) acc[mb][nb][v] = 0.f;

    uint32_t arow = (uint32_t)(wm * 32 + (lane & 15));
    uint32_t aoff = arow * (ASTR * 2) + ((lane >> 4) << 4);
    uint32_t brow = (uint32_t)(wn * 32 + (lane & 7) + ((lane >> 4) << 3));
    uint32_t boff = brow * (ASTR * 2) + (((lane >> 3) & 1) << 4);

#pragma unroll
    for (int s = 0; s < 8; s++) {
        uint32_t kb = (uint32_t)(s * 32);
        uint32_t a0[4], a1[4], b0[4], b1[4];
        ldsm_x4(a0[0], a0[1], a0[2], a0[3], sbA + aoff + kb);
        ldsm_x4(a1[0], a1[1], a1[2], a1[3], sbA + aoff + 16 * (ASTR * 2) + kb);
        ldsm_x4(b0[0], b0[1], b0[2], b0[3], sbB + boff + kb);
        ldsm_x4(b1[0], b1[1], b1[2], b1[3], sbB + boff + 16 * (ASTR * 2) + kb);
#pragma unroll
        for (int mb = 0; mb < 2; mb++) {
            uint32_t* a = (mb == 0) ? a0 : a1;
            mma_bf16(acc[mb][0][0], acc[mb][0][1], acc[mb][0][2], acc[mb][0][3],
                     a[0], a[1], a[2], a[3], b0[0], b0[1]);
            mma_bf16(acc[mb][1][0], acc[mb][1][1], acc[mb][1][2], acc[mb][1][3],
                     a[0], a[1], a[2], a[3], b0[2], b0[3]);
            mma_bf16(acc[mb][2][0], acc[mb][2][1], acc[mb][2][2], acc[mb][2][3],
                     a[0], a[1], a[2], a[3], b1[0], b1[1]);
            mma_bf16(acc[mb][3][0], acc[mb][3][1], acc[mb][3][2], acc[mb][3][3],
                     a[0], a[1], a[2], a[3], b1[2], b1[3]);
        }
    }

    float sr = 0.f, srr = 0.f, srd = 0.f, sd = 0.f, sdd = 0.f;
    int r4 = lane >> 2, c2 = (lane & 3) * 2;
#pragma unroll
    for (int mb = 0; mb < 2; mb++) {
#pragma unroll
        for (int nb = 0; nb < 4; nb++) {
#pragma unroll
            for (int v = 0; v < 4; v++) {
                int il = wm * 32 + mb * 16 + r4 + ((v >> 1) << 3);
                int jl = wn * 32 + nb * 8 + c2 + (v & 1);
                int gi = i0 + il, gj = j0 + jl;
                if (gi < KK && gj < gi) {
                    float rv = acc[mb][nb][v];
                    float2 P = posi[il];
                    float2 Q = posje[jl];
                    float dx = P.x - Q.x, dy = P.y - Q.y;
                    float ds = 1.0f / (sqrtf(dx * dx + dy * dy) + 1.0f);
                    sr += rv; srr += rv * rv; srd += rv * ds;
                    sd += ds; sdd += ds * ds;
                }
            }
        }
    }

    float vals[5] = {sr, srr, srd, sd, sdd};
    __shared__ double red[4][5];
#pragma unroll
    for (int v = 0; v < 5; v++) {
        float x = vals[v];
#pragma unroll
        for (int o = 16; o; o >>= 1) x += __shfl_xor_sync(0xFFFFFFFFu, x, o);
        if (lane == 0) red[wid][v] = (double)x;
    }
    __syncthreads();
    if (tid < 5) {
        double s = red[0][tid] + red[1][tid] + red[2][tid] + red[3][tid];
        atomicAdd(&g_acc[run][tid], s);
    }
    __syncthreads();

    // fused finalize: last block (ticket) runs cold float-only epilogue
    __shared__ unsigned s_ticket;
    if (tid == 0) {
        __threadfence();
        s_ticket = atomicAdd(&g_done, 1u);
    }
    __syncthreads();
    if (s_ticket == NBLK - 1 && tid == 0) {
        __threadfence();
        do_finalize(out);
    }
}

// ---------------- launch ----------------
extern "C" void kernel_launch(void* const* d_in, const int* in_sizes, int n_in,
                              void* d_out, int out_size) {
    const float* feats = (const float*)d_in[0];   // (128, 100000) f32
    const float* pos   = (const float*)d_in[1];   // (100000, 2)   f32
    const int*   neigh = (const int*)  d_in[2];   // (100, 500)    i32

    cudaFuncSetAttribute(k_pairs, cudaFuncAttributeMaxDynamicSharedMemorySize,
                         SM_TOTAL);

    k_gather<<<dim3(32, NRUNS), 256>>>(feats, pos, neigh);
    k_pairs<<<NBLK, 128, SM_TOTAL>>>((float*)d_out);
}